// round 2
// baseline (speedup 1.0000x reference)
#include <cuda_runtime.h>
#include <cuda_fp16.h>
#include <cstdint>

// Problem dims
#define NN   8192
#define DIN  128
#define DOUT 64

// GEMM tiling
#define M_TILE  256
#define K_TILE  32
#define SPLITK  4
#define KPER    (NN / SPLITK)      // 2048
#define NCHUNK  (KPER / K_TILE)    // 64

// smem layout (dynamic): A stages padded to 128B rows (256 rows x 64 fp16 slots)
#define A_STAGE_BYTES (M_TILE * 128)      // 32 KB
#define B_STAGE_BYTES (K_TILE * 128)      // 4 KB  (32 rows x 64 fp16)
#define SMEM_A0 0
#define SMEM_A1 (A_STAGE_BYTES)
#define SMEM_B0 (2 * A_STAGE_BYTES)
#define SMEM_B1 (2 * A_STAGE_BYTES + B_STAGE_BYTES)
#define SMEM_TOTAL (2 * A_STAGE_BYTES + 2 * B_STAGE_BYTES)   // 73728

// Scratch (no cudaMalloc allowed)
__device__ __align__(16)  float  g_deg[NN];
__device__ __align__(16)  __half g_yh[(size_t)NN * DOUT];                 // Y = d^-1/2 * (X@W), fp16
__device__ __align__(16)  float  g_hpart[SPLITK][(size_t)NN * DOUT];      // split-K partials

// ---------------------------------------------------------------------------
// PTX helpers (generic PTX only — compute_103 base target, no 'a' features)
// ---------------------------------------------------------------------------
__device__ __forceinline__ uint32_t smem_u32(const void* p) {
    uint32_t a;
    asm("{ .reg .u64 t; cvta.to.shared.u64 t, %1; cvt.u32.u64 %0, t; }" : "=r"(a) : "l"(p));
    return a;
}

#define CP_ASYNC16(dst, src) \
    asm volatile("cp.async.cg.shared.global [%0], [%1], 16;" :: "r"(dst), "l"(src) : "memory")
#define CP_COMMIT() asm volatile("cp.async.commit_group;" ::: "memory")
#define CP_WAIT0()  asm volatile("cp.async.wait_group 0;" ::: "memory")

__device__ __forceinline__ void ldsm_x4(uint32_t r[4], uint32_t addr) {
    asm volatile("ldmatrix.sync.aligned.m8n8.x4.shared.b16 {%0,%1,%2,%3}, [%4];"
                 : "=r"(r[0]), "=r"(r[1]), "=r"(r[2]), "=r"(r[3]) : "r"(addr));
}
__device__ __forceinline__ void ldsm_x4_t(uint32_t r[4], uint32_t addr) {
    asm volatile("ldmatrix.sync.aligned.m8n8.x4.trans.shared.b16 {%0,%1,%2,%3}, [%4];"
                 : "=r"(r[0]), "=r"(r[1]), "=r"(r[2]), "=r"(r[3]) : "r"(addr));
}
__device__ __forceinline__ void mma_f16(float c[4], const uint32_t a[4], uint32_t b0, uint32_t b1) {
    asm volatile(
        "mma.sync.aligned.m16n8k16.row.col.f32.f16.f16.f32 "
        "{%0,%1,%2,%3}, {%4,%5,%6,%7}, {%8,%9}, {%0,%1,%2,%3};"
        : "+f"(c[0]), "+f"(c[1]), "+f"(c[2]), "+f"(c[3])
        : "r"(a[0]), "r"(a[1]), "r"(a[2]), "r"(a[3]), "r"(b0), "r"(b1));
}

// ---------------------------------------------------------------------------
// Kernel 1: deg[i] = rowsum(A[i])
// ---------------------------------------------------------------------------
__global__ void rowsum_kernel(const float* __restrict__ A) {
    int row = blockIdx.x;
    const float4* a = reinterpret_cast<const float4*>(A + (size_t)row * NN);
    float s = 0.f;
    #pragma unroll 4
    for (int i = threadIdx.x; i < NN / 4; i += 256) {
        float4 v = a[i];
        s += (v.x + v.y) + (v.z + v.w);
    }
    #pragma unroll
    for (int o = 16; o; o >>= 1) s += __shfl_xor_sync(0xFFFFFFFFu, s, o);
    __shared__ float red[8];
    if ((threadIdx.x & 31) == 0) red[threadIdx.x >> 5] = s;
    __syncthreads();
    if (threadIdx.x < 32) {
        s = (threadIdx.x < 8) ? red[threadIdx.x] : 0.f;
        #pragma unroll
        for (int o = 4; o; o >>= 1) s += __shfl_xor_sync(0xFFFFFFFFu, s, o);
        if (threadIdx.x == 0) g_deg[row] = s;
    }
}

// ---------------------------------------------------------------------------
// Kernel 2: Y[j][k] = fp16( rsqrt(deg[j]) * sum_f X[j][f] * W[f][k] )
// block 256 thr handles 16 rows; grid 512
// ---------------------------------------------------------------------------
__global__ void xw_kernel(const float* __restrict__ X, const float* __restrict__ W) {
    __shared__ float sW[DIN * DOUT];   // 32 KB
    __shared__ float sX[16 * DIN];     // 8 KB
    int r0 = blockIdx.x * 16;
    for (int i = threadIdx.x; i < DIN * DOUT; i += 256) sW[i] = W[i];
    for (int i = threadIdx.x; i < 16 * DIN; i += 256) {
        int r = i >> 7, f = i & 127;
        sX[i] = X[(size_t)(r0 + r) * DIN + f] * rsqrtf(g_deg[r0 + r]);
    }
    __syncthreads();

    int r  = threadIdx.x >> 4;           // 0..15
    int c0 = (threadIdx.x & 15) * 4;     // 0..60
    float4 acc = make_float4(0.f, 0.f, 0.f, 0.f);
    #pragma unroll 8
    for (int f = 0; f < DIN; f++) {
        float s = sX[r * DIN + f];
        float4 w = *reinterpret_cast<const float4*>(&sW[f * DOUT + c0]);
        acc.x += s * w.x; acc.y += s * w.y; acc.z += s * w.z; acc.w += s * w.w;
    }
    __half2 h01 = __floats2half2_rn(acc.x, acc.y);
    __half2 h23 = __floats2half2_rn(acc.z, acc.w);
    uint2 u;
    u.x = *reinterpret_cast<uint32_t*>(&h01);
    u.y = *reinterpret_cast<uint32_t*>(&h23);
    *reinterpret_cast<uint2*>(&g_yh[(size_t)(r0 + r) * DOUT + c0]) = u;
}

// ---------------------------------------------------------------------------
// Kernel 3: split-K GEMM  g_hpart[split] = A_slice @ Y_slice   (fp16 mma.sync)
// grid (32, 4), block 256 (8 warps: 4 over M x 2 over N)
// ---------------------------------------------------------------------------
__global__ void __launch_bounds__(256, 1)
gemm_kernel(const float* __restrict__ A) {
    extern __shared__ __align__(128) char smem[];
    const uint32_t sbase = smem_u32(smem);

    const int tid  = threadIdx.x;
    const int lane = tid & 31;
    const int wid  = tid >> 5;
    const int wm   = wid & 3;            // warp M group (64 rows)
    const int wn   = wid >> 2;           // warp N group (32 cols)
    const int Ar0  = wm * 64;            // local row base in A tile
    const int Cn0  = wn * 32;            // local col base in B tile

    const float*  Ablk = A + (size_t)blockIdx.x * M_TILE * NN + (size_t)blockIdx.y * KPER;
    const __half* Bblk = g_yh + (size_t)blockIdx.y * KPER * DOUT;

    // per-thread A-load geometry: 8 passes, 4 rows/warp/pass, 8 lanes per row
    const int arow = tid >> 3;                   // 0..31 (+32*p)
    const int acf4 = tid & 7;                    // float4 index in the 32-col chunk
    const uint32_t asw = ((uint32_t)((acf4 >> 1) ^ (arow & 7)) << 4) + (uint32_t)((acf4 & 1) * 8);

    // per-thread B cp.async geometry (1 x 16B per thread per chunk)
    const int bkrow = tid >> 3;                  // 0..31
    const int bcc   = tid & 7;
    const uint32_t bsw = (uint32_t)bkrow * 128 + ((uint32_t)(bcc ^ (bkrow & 7)) << 4);
    const __half* bsrc0 = Bblk + (size_t)bkrow * DOUT + bcc * 8;

    // ldmatrix per-lane geometry
    const int a_lrow = lane & 15;
    const int a_lk   = (lane >> 4) * 8;
    const int b_lk   = lane & 15;
    const int b_ln   = (lane >> 4) * 8;

    float acc[4][4][4];
    #pragma unroll
    for (int mi = 0; mi < 4; mi++)
        #pragma unroll
        for (int ni = 0; ni < 4; ni++)
            #pragma unroll
            for (int q = 0; q < 4; q++) acc[mi][ni][q] = 0.f;

    float4 areg[8];

    // ---- prologue: chunk 0 into stage 0 ----
    {
        const float* ap = Ablk;
        #pragma unroll
        for (int p = 0; p < 8; p++)
            areg[p] = *reinterpret_cast<const float4*>(ap + (size_t)(arow + 32 * p) * NN + acf4 * 4);
        CP_ASYNC16(sbase + SMEM_B0 + bsw, bsrc0);
        CP_COMMIT();
        #pragma unroll
        for (int p = 0; p < 8; p++) {
            __half2 h01 = __floats2half2_rn(areg[p].x, areg[p].y);
            __half2 h23 = __floats2half2_rn(areg[p].z, areg[p].w);
            uint2 u;
            u.x = *reinterpret_cast<uint32_t*>(&h01);
            u.y = *reinterpret_cast<uint32_t*>(&h23);
            *reinterpret_cast<uint2*>(smem + SMEM_A0 + (uint32_t)(arow + 32 * p) * 128 + asw) = u;
        }
        CP_WAIT0();
        __syncthreads();
    }

    for (int c = 0; c < NCHUNK; c++) {
        const int s = c & 1;
        const uint32_t sA = sbase + (s ? SMEM_A1 : SMEM_A0);
        const uint32_t sB = sbase + (s ? SMEM_B1 : SMEM_B0);
        const uint32_t sAn = sbase + (s ? SMEM_A0 : SMEM_A1);
        const uint32_t sBn = sbase + (s ? SMEM_B0 : SMEM_B1);
        const bool more = (c + 1 < NCHUNK);

        // prefetch chunk c+1 (LDG -> regs, cp.async B)
        if (more) {
            const float* ap = Ablk + (size_t)(c + 1) * K_TILE;
            #pragma unroll
            for (int p = 0; p < 8; p++)
                areg[p] = *reinterpret_cast<const float4*>(ap + (size_t)(arow + 32 * p) * NN + acf4 * 4);
            CP_ASYNC16(sBn + bsw, bsrc0 + (size_t)(c + 1) * K_TILE * DOUT);
            CP_COMMIT();
        }

        // compute chunk c from stage s
        #pragma unroll
        for (int kk = 0; kk < K_TILE; kk += 16) {
            uint32_t af[4][4];
            #pragma unroll
            for (int mi = 0; mi < 4; mi++) {
                int r = Ar0 + mi * 16 + a_lrow;
                uint32_t addr = sA + (uint32_t)r * 128 +
                                ((uint32_t)((((kk + a_lk) >> 3)) ^ (r & 7)) << 4);
                ldsm_x4(af[mi], addr);
            }
            uint32_t bf[2][4];
            #pragma unroll
            for (int nb = 0; nb < 2; nb++) {
                int kr = kk + b_lk;
                int n  = Cn0 + nb * 16 + b_ln;
                uint32_t addr = sB + (uint32_t)kr * 128 +
                                ((uint32_t)((n >> 3) ^ (kr & 7)) << 4);
                ldsm_x4_t(bf[nb], addr);
            }
            #pragma unroll
            for (int mi = 0; mi < 4; mi++)
                #pragma unroll
                for (int ni = 0; ni < 4; ni++)
                    mma_f16(acc[mi][ni], af[mi], bf[ni >> 1][2 * (ni & 1)], bf[ni >> 1][2 * (ni & 1) + 1]);
        }

        if (more) {
            // store prefetched A (fp32 -> fp16) into next stage
            #pragma unroll
            for (int p = 0; p < 8; p++) {
                __half2 h01 = __floats2half2_rn(areg[p].x, areg[p].y);
                __half2 h23 = __floats2half2_rn(areg[p].z, areg[p].w);
                uint2 u;
                u.x = *reinterpret_cast<uint32_t*>(&h01);
                u.y = *reinterpret_cast<uint32_t*>(&h23);
                asm volatile("st.shared.v2.b32 [%0], {%1, %2};"
                             :: "r"(sAn + (uint32_t)(arow + 32 * p) * 128 + asw), "r"(u.x), "r"(u.y)
                             : "memory");
            }
            CP_WAIT0();
            __syncthreads();
        }
    }

    // ---- epilogue: acc -> g_hpart[split] ----
    float* Hp = g_hpart[blockIdx.y];
    const int g = lane >> 2, q = lane & 3;
    const int R0 = blockIdx.x * M_TILE + wm * 64;
    #pragma unroll
    for (int mi = 0; mi < 4; mi++) {
        #pragma unroll
        for (int ni = 0; ni < 4; ni++) {
            int row = R0 + mi * 16 + g;
            int col = Cn0 + ni * 8 + q * 2;
            *reinterpret_cast<float2*>(&Hp[(size_t)row * DOUT + col]) =
                make_float2(acc[mi][ni][0], acc[mi][ni][1]);
            *reinterpret_cast<float2*>(&Hp[(size_t)(row + 8) * DOUT + col]) =
                make_float2(acc[mi][ni][2], acc[mi][ni][3]);
        }
    }
}

// ---------------------------------------------------------------------------
// Kernel 4: out = relu( d^-1/2_i * sum_s hpart[s] )
// ---------------------------------------------------------------------------
__global__ void out_kernel(float* __restrict__ out) {
    int idx = blockIdx.x * 256 + threadIdx.x;      // over 8192*16 float4s
    int row = idx >> 4;
    int c4  = (idx & 15) * 4;
    size_t o = (size_t)row * DOUT + c4;
    float4 a = *reinterpret_cast<const float4*>(&g_hpart[0][o]);
    float4 b = *reinterpret_cast<const float4*>(&g_hpart[1][o]);
    float4 cc = *reinterpret_cast<const float4*>(&g_hpart[2][o]);
    float4 d = *reinterpret_cast<const float4*>(&g_hpart[3][o]);
    float s = rsqrtf(g_deg[row]);
    float4 r;
    r.x = fmaxf((a.x + b.x + cc.x + d.x) * s, 0.f);
    r.y = fmaxf((a.y + b.y + cc.y + d.y) * s, 0.f);
    r.z = fmaxf((a.z + b.z + cc.z + d.z) * s, 0.f);
    r.w = fmaxf((a.w + b.w + cc.w + d.w) * s, 0.f);
    *reinterpret_cast<float4*>(&out[o]) = r;
}

// ---------------------------------------------------------------------------
// Launch
// ---------------------------------------------------------------------------
extern "C" void kernel_launch(void* const* d_in, const int* in_sizes, int n_in,
                              void* d_out, int out_size) {
    const float* X = (const float*)d_in[0];   // features      [8192, 128]
    const float* A = (const float*)d_in[1];   // adjacency     [8192, 8192]
    const float* W = (const float*)d_in[2];   // weight        [128, 64]
    float* out = (float*)d_out;               // [8192, 64] fp32
    (void)in_sizes; (void)n_in; (void)out_size;

    static bool attr_set = false;
    if (!attr_set) {
        cudaFuncSetAttribute(gemm_kernel, cudaFuncAttributeMaxDynamicSharedMemorySize, SMEM_TOTAL);
        attr_set = true;
    }

    rowsum_kernel<<<NN, 256>>>(A);
    xw_kernel<<<NN / 16, 256>>>(X, W);
    gemm_kernel<<<dim3(NN / M_TILE, SPLITK), 256, SMEM_TOTAL>>>(A);
    out_kernel<<<(NN * 16) / 256, 256>>>(out);
}

// round 4
// speedup vs baseline: 1.2259x; 1.2259x over previous
#include <cuda_runtime.h>
#include <cuda_fp16.h>
#include <cstdint>

// Problem dims
#define NN   8192
#define DIN  128
#define DOUT 64

// GEMM tiling
#define M_TILE  256
#define K_TILE  64
#define SPLITK  4
#define KPER    (NN / SPLITK)      // 2048
#define NCHUNK  (KPER / K_TILE)    // 32
#define STAGES  4

// smem: A stage = 256 rows x 128B (64 fp16), B stage = 64 rows x 128B
#define A_STAGE_BYTES (M_TILE * 128)            // 32 KB
#define B_STAGE_BYTES (K_TILE * 128)            // 8 KB
#define SMEM_B_BASE   (STAGES * A_STAGE_BYTES)  // 128 KB
#define SMEM_TOTAL    (STAGES * (A_STAGE_BYTES + B_STAGE_BYTES))  // 160 KB

// Scratch (no cudaMalloc allowed)
__device__ __align__(16)  float  g_deg[NN];
__device__ __align__(16)  __half g_ah[(size_t)NN * NN];                   // fp16 copy of A
__device__ __align__(16)  __half g_yh[(size_t)NN * DOUT];                 // Y = d^-1/2*(X@W), fp16
__device__ __align__(16)  float  g_hpart[SPLITK][(size_t)NN * DOUT];      // split-K partials

// ---------------------------------------------------------------------------
// PTX helpers (generic PTX only — harness compiles through compute_103 base)
// ---------------------------------------------------------------------------
__device__ __forceinline__ uint32_t smem_u32(const void* p) {
    uint32_t a;
    asm("{ .reg .u64 t; cvta.to.shared.u64 t, %1; cvt.u32.u64 %0, t; }" : "=r"(a) : "l"(p));
    return a;
}

#define CP_ASYNC16(dst, src) \
    asm volatile("cp.async.cg.shared.global [%0], [%1], 16;" :: "r"(dst), "l"(src) : "memory")
#define CP_COMMIT() asm volatile("cp.async.commit_group;" ::: "memory")
#define CP_WAIT2()  asm volatile("cp.async.wait_group 2;" ::: "memory")

__device__ __forceinline__ void ldsm_x4(uint32_t r[4], uint32_t addr) {
    asm volatile("ldmatrix.sync.aligned.m8n8.x4.shared.b16 {%0,%1,%2,%3}, [%4];"
                 : "=r"(r[0]), "=r"(r[1]), "=r"(r[2]), "=r"(r[3]) : "r"(addr));
}
__device__ __forceinline__ void ldsm_x4_t(uint32_t r[4], uint32_t addr) {
    asm volatile("ldmatrix.sync.aligned.m8n8.x4.trans.shared.b16 {%0,%1,%2,%3}, [%4];"
                 : "=r"(r[0]), "=r"(r[1]), "=r"(r[2]), "=r"(r[3]) : "r"(addr));
}
__device__ __forceinline__ void mma_f16(float c[4], const uint32_t a[4], uint32_t b0, uint32_t b1) {
    asm volatile(
        "mma.sync.aligned.m16n8k16.row.col.f32.f16.f16.f32 "
        "{%0,%1,%2,%3}, {%4,%5,%6,%7}, {%8,%9}, {%0,%1,%2,%3};"
        : "+f"(c[0]), "+f"(c[1]), "+f"(c[2]), "+f"(c[3])
        : "r"(a[0]), "r"(a[1]), "r"(a[2]), "r"(a[3]), "r"(b0), "r"(b1));
}

// ---------------------------------------------------------------------------
// Kernel 1: deg[i] = rowsum(A[i]); also writes A_h = fp16(A)
// ---------------------------------------------------------------------------
__global__ void __launch_bounds__(256)
rowsum_convert_kernel(const float* __restrict__ A) {
    int row = blockIdx.x;
    const float4* a = reinterpret_cast<const float4*>(A + (size_t)row * NN);
    uint2* ah = reinterpret_cast<uint2*>(g_ah + (size_t)row * NN);
    float s = 0.f;
    #pragma unroll 8
    for (int i = threadIdx.x; i < NN / 4; i += 256) {
        float4 v = a[i];
        s += (v.x + v.y) + (v.z + v.w);
        __half2 h01 = __floats2half2_rn(v.x, v.y);
        __half2 h23 = __floats2half2_rn(v.z, v.w);
        uint2 u;
        u.x = *reinterpret_cast<uint32_t*>(&h01);
        u.y = *reinterpret_cast<uint32_t*>(&h23);
        ah[i] = u;
    }
    #pragma unroll
    for (int o = 16; o; o >>= 1) s += __shfl_xor_sync(0xFFFFFFFFu, s, o);
    __shared__ float red[8];
    if ((threadIdx.x & 31) == 0) red[threadIdx.x >> 5] = s;
    __syncthreads();
    if (threadIdx.x < 32) {
        s = (threadIdx.x < 8) ? red[threadIdx.x] : 0.f;
        #pragma unroll
        for (int o = 4; o; o >>= 1) s += __shfl_xor_sync(0xFFFFFFFFu, s, o);
        if (threadIdx.x == 0) g_deg[row] = s;
    }
}

// ---------------------------------------------------------------------------
// Kernel 2: Y[j][k] = fp16( rsqrt(deg[j]) * sum_f X[j][f] * W[f][k] )
// ---------------------------------------------------------------------------
__global__ void xw_kernel(const float* __restrict__ X, const float* __restrict__ W) {
    __shared__ float sW[DIN * DOUT];   // 32 KB
    __shared__ float sX[16 * DIN];     // 8 KB
    int r0 = blockIdx.x * 16;
    for (int i = threadIdx.x; i < DIN * DOUT; i += 256) sW[i] = W[i];
    for (int i = threadIdx.x; i < 16 * DIN; i += 256) {
        int r = i >> 7, f = i & 127;
        sX[i] = X[(size_t)(r0 + r) * DIN + f] * rsqrtf(g_deg[r0 + r]);
    }
    __syncthreads();

    int r  = threadIdx.x >> 4;           // 0..15
    int c0 = (threadIdx.x & 15) * 4;     // 0..60
    float4 acc = make_float4(0.f, 0.f, 0.f, 0.f);
    #pragma unroll 8
    for (int f = 0; f < DIN; f++) {
        float s = sX[r * DIN + f];
        float4 w = *reinterpret_cast<const float4*>(&sW[f * DOUT + c0]);
        acc.x += s * w.x; acc.y += s * w.y; acc.z += s * w.z; acc.w += s * w.w;
    }
    __half2 h01 = __floats2half2_rn(acc.x, acc.y);
    __half2 h23 = __floats2half2_rn(acc.z, acc.w);
    uint2 u;
    u.x = *reinterpret_cast<uint32_t*>(&h01);
    u.y = *reinterpret_cast<uint32_t*>(&h23);
    *reinterpret_cast<uint2*>(&g_yh[(size_t)(r0 + r) * DOUT + c0]) = u;
}

// ---------------------------------------------------------------------------
// Kernel 3: split-K GEMM  g_hpart[split] = A_h_slice @ Y_slice (fp16 mma.sync)
// grid (32, 4), block 256 (8 warps: 4 over M x 2 over N), 4-stage pipeline
// ---------------------------------------------------------------------------
__device__ __forceinline__ void load_chunk(uint32_t sbase, int stage, int c,
                                           const __half* __restrict__ Ablk,
                                           const __half* __restrict__ Bblk, int tid) {
    const uint32_t sA = sbase + (uint32_t)stage * A_STAGE_BYTES;
    const uint32_t sB = sbase + SMEM_B_BASE + (uint32_t)stage * B_STAGE_BYTES;
    const __half* ap = Ablk + (size_t)c * K_TILE;
    const __half* bp = Bblk + (size_t)c * K_TILE * DOUT;
    // A: 256 rows x 128B -> 2048 x 16B -> 8 per thread
    #pragma unroll
    for (int it = 0; it < 8; it++) {
        int idx = tid + 256 * it;
        int row = idx >> 3;
        int cc  = idx & 7;
        uint32_t dst = sA + (uint32_t)row * 128 + ((uint32_t)(cc ^ (row & 7)) << 4);
        CP_ASYNC16(dst, ap + (size_t)row * NN + cc * 8);
    }
    // B: 64 rows x 128B -> 512 x 16B -> 2 per thread
    #pragma unroll
    for (int it = 0; it < 2; it++) {
        int idx = tid + 256 * it;
        int kr  = idx >> 3;
        int cc  = idx & 7;
        uint32_t dst = sB + (uint32_t)kr * 128 + ((uint32_t)(cc ^ (kr & 7)) << 4);
        CP_ASYNC16(dst, bp + (size_t)kr * DOUT + cc * 8);
    }
}

__global__ void __launch_bounds__(256, 1)
gemm_kernel() {
    extern __shared__ __align__(128) char smem[];
    const uint32_t sbase = smem_u32(smem);

    const int tid  = threadIdx.x;
    const int lane = tid & 31;
    const int wid  = tid >> 5;
    const int wm   = wid & 3;            // warp M group (64 rows)
    const int wn   = wid >> 2;           // warp N group (32 cols)
    const int Ar0  = wm * 64;
    const int Cn0  = wn * 32;

    const __half* Ablk = g_ah + (size_t)blockIdx.x * M_TILE * NN + (size_t)blockIdx.y * KPER;
    const __half* Bblk = g_yh + (size_t)blockIdx.y * KPER * DOUT;

    // ldmatrix per-lane geometry
    const int a_lrow = lane & 15;
    const int a_lk   = lane >> 4;        // 0/1 -> k 16B col-chunk
    const int b_lk   = lane & 15;
    const int b_ln8  = lane >> 4;        // 0/1 -> n 8-group

    float acc[4][4][4];
    #pragma unroll
    for (int mi = 0; mi < 4; mi++)
        #pragma unroll
        for (int ni = 0; ni < 4; ni++)
            #pragma unroll
            for (int q = 0; q < 4; q++) acc[mi][ni][q] = 0.f;

    // prologue: stages 0..2
    #pragma unroll
    for (int s = 0; s < STAGES - 1; s++) {
        load_chunk(sbase, s, s, Ablk, Bblk, tid);
        CP_COMMIT();
    }

    for (int c = 0; c < NCHUNK; c++) {
        CP_WAIT2();                       // exactly 3 groups pending -> chunk c resident
        __syncthreads();

        const int s = c & (STAGES - 1);
        const uint32_t sA = sbase + (uint32_t)s * A_STAGE_BYTES;
        const uint32_t sB = sbase + SMEM_B_BASE + (uint32_t)s * B_STAGE_BYTES;

        // RACE FIX: commit a group EVERY iteration (empty groups at the tail),
        // so wait_group 2 above always drains the group carrying chunk c.
        if (c + STAGES - 1 < NCHUNK)
            load_chunk(sbase, (c + STAGES - 1) & (STAGES - 1), c + STAGES - 1, Ablk, Bblk, tid);
        CP_COMMIT();

        #pragma unroll
        for (int kk = 0; kk < K_TILE / 16; kk++) {
            uint32_t af[4][4];
            #pragma unroll
            for (int mi = 0; mi < 4; mi++) {
                int r = Ar0 + mi * 16 + a_lrow;
                uint32_t addr = sA + (uint32_t)r * 128 +
                                ((uint32_t)((kk * 2 + a_lk) ^ (r & 7)) << 4);
                ldsm_x4(af[mi], addr);
            }
            uint32_t bf[2][4];
            #pragma unroll
            for (int nb = 0; nb < 2; nb++) {
                int kr = kk * 16 + b_lk;
                int n  = Cn0 + nb * 16 + b_ln8 * 8;
                uint32_t addr = sB + (uint32_t)kr * 128 +
                                ((uint32_t)((n >> 3) ^ (kr & 7)) << 4);
                ldsm_x4_t(bf[nb], addr);
            }
            #pragma unroll
            for (int mi = 0; mi < 4; mi++)
                #pragma unroll
                for (int ni = 0; ni < 4; ni++)
                    mma_f16(acc[mi][ni], af[mi], bf[ni >> 1][2 * (ni & 1)], bf[ni >> 1][2 * (ni & 1) + 1]);
        }
    }

    // epilogue: acc -> g_hpart[split]
    float* Hp = g_hpart[blockIdx.y];
    const int g = lane >> 2, q = lane & 3;
    const int R0 = blockIdx.x * M_TILE + wm * 64;
    #pragma unroll
    for (int mi = 0; mi < 4; mi++) {
        #pragma unroll
        for (int ni = 0; ni < 4; ni++) {
            int row = R0 + mi * 16 + g;
            int col = Cn0 + ni * 8 + q * 2;
            *reinterpret_cast<float2*>(&Hp[(size_t)row * DOUT + col]) =
                make_float2(acc[mi][ni][0], acc[mi][ni][1]);
            *reinterpret_cast<float2*>(&Hp[(size_t)(row + 8) * DOUT + col]) =
                make_float2(acc[mi][ni][2], acc[mi][ni][3]);
        }
    }
}

// ---------------------------------------------------------------------------
// Kernel 4: out = relu( d^-1/2_i * sum_s hpart[s] )
// ---------------------------------------------------------------------------
__global__ void out_kernel(float* __restrict__ out) {
    int idx = blockIdx.x * 256 + threadIdx.x;      // over 8192*16 float4s
    int row = idx >> 4;
    int c4  = (idx & 15) * 4;
    size_t o = (size_t)row * DOUT + c4;
    float4 a = *reinterpret_cast<const float4*>(&g_hpart[0][o]);
    float4 b = *reinterpret_cast<const float4*>(&g_hpart[1][o]);
    float4 cc = *reinterpret_cast<const float4*>(&g_hpart[2][o]);
    float4 d = *reinterpret_cast<const float4*>(&g_hpart[3][o]);
    float s = rsqrtf(g_deg[row]);
    float4 r;
    r.x = fmaxf((a.x + b.x + cc.x + d.x) * s, 0.f);
    r.y = fmaxf((a.y + b.y + cc.y + d.y) * s, 0.f);
    r.z = fmaxf((a.z + b.z + cc.z + d.z) * s, 0.f);
    r.w = fmaxf((a.w + b.w + cc.w + d.w) * s, 0.f);
    *reinterpret_cast<float4*>(&out[o]) = r;
}

// ---------------------------------------------------------------------------
// Launch
// ---------------------------------------------------------------------------
extern "C" void kernel_launch(void* const* d_in, const int* in_sizes, int n_in,
                              void* d_out, int out_size) {
    const float* X = (const float*)d_in[0];   // features      [8192, 128]
    const float* A = (const float*)d_in[1];   // adjacency     [8192, 8192]
    const float* W = (const float*)d_in[2];   // weight        [128, 64]
    float* out = (float*)d_out;               // [8192, 64] fp32
    (void)in_sizes; (void)n_in; (void)out_size;

    static bool attr_set = false;
    if (!attr_set) {
        cudaFuncSetAttribute(gemm_kernel, cudaFuncAttributeMaxDynamicSharedMemorySize, SMEM_TOTAL);
        attr_set = true;
    }

    rowsum_convert_kernel<<<NN, 256>>>(A);
    xw_kernel<<<NN / 16, 256>>>(X, W);
    gemm_kernel<<<dim3(NN / M_TILE, SPLITK), 256, SMEM_TOTAL>>>();
    out_kernel<<<(NN * 16) / 256, 256>>>(out);
}

// round 5
// speedup vs baseline: 1.2346x; 1.0071x over previous
#include <cuda_runtime.h>
#include <cuda_fp16.h>
#include <cstdint>

// Problem dims
#define NN   8192
#define DIN  128
#define DOUT 64

// GEMM tiling
#define M_TILE  128
#define K_TILE  64
#define SPLITK  4
#define KPER    (NN / SPLITK)      // 2048
#define NCHUNK  (KPER / K_TILE)    // 32
#define STAGES  4

// smem: A stage = 128 rows x 128B (64 fp16), B stage = 64 rows x 128B
#define A_STAGE_BYTES (M_TILE * 128)            // 16 KB
#define B_STAGE_BYTES (K_TILE * 128)            // 8 KB
#define SMEM_B_BASE   (STAGES * A_STAGE_BYTES)  // 64 KB
#define SMEM_TOTAL    (STAGES * (A_STAGE_BYTES + B_STAGE_BYTES))  // 96 KB -> 2 CTAs/SM

// Scratch (no cudaMalloc allowed)
__device__ __align__(16)  float  g_deg[NN];
__device__ __align__(16)  __half g_ah[(size_t)NN * NN];                   // fp16 copy of A
__device__ __align__(16)  __half g_yh[(size_t)NN * DOUT];                 // Y = d^-1/2*(X@W), fp16
__device__ __align__(16)  float  g_hpart[SPLITK][(size_t)NN * DOUT];      // split-K partials

// ---------------------------------------------------------------------------
// PTX helpers (generic PTX only — harness compiles through compute_103 base)
// ---------------------------------------------------------------------------
__device__ __forceinline__ uint32_t smem_u32(const void* p) {
    uint32_t a;
    asm("{ .reg .u64 t; cvta.to.shared.u64 t, %1; cvt.u32.u64 %0, t; }" : "=r"(a) : "l"(p));
    return a;
}

#define CP_ASYNC16(dst, src) \
    asm volatile("cp.async.cg.shared.global [%0], [%1], 16;" :: "r"(dst), "l"(src) : "memory")
#define CP_COMMIT() asm volatile("cp.async.commit_group;" ::: "memory")
#define CP_WAIT2()  asm volatile("cp.async.wait_group 2;" ::: "memory")

__device__ __forceinline__ void ldsm_x4(uint32_t r[4], uint32_t addr) {
    asm volatile("ldmatrix.sync.aligned.m8n8.x4.shared.b16 {%0,%1,%2,%3}, [%4];"
                 : "=r"(r[0]), "=r"(r[1]), "=r"(r[2]), "=r"(r[3]) : "r"(addr));
}
__device__ __forceinline__ void ldsm_x4_t(uint32_t r[4], uint32_t addr) {
    asm volatile("ldmatrix.sync.aligned.m8n8.x4.trans.shared.b16 {%0,%1,%2,%3}, [%4];"
                 : "=r"(r[0]), "=r"(r[1]), "=r"(r[2]), "=r"(r[3]) : "r"(addr));
}
__device__ __forceinline__ void mma_f16(float c[4], const uint32_t a[4], uint32_t b0, uint32_t b1) {
    asm volatile(
        "mma.sync.aligned.m16n8k16.row.col.f32.f16.f16.f32 "
        "{%0,%1,%2,%3}, {%4,%5,%6,%7}, {%8,%9}, {%0,%1,%2,%3};"
        : "+f"(c[0]), "+f"(c[1]), "+f"(c[2]), "+f"(c[3])
        : "r"(a[0]), "r"(a[1]), "r"(a[2]), "r"(a[3]), "r"(b0), "r"(b1));
}

// ---------------------------------------------------------------------------
// Kernel 1: deg[i] = rowsum(A[i]); also writes A_h = fp16(A)
// grid-stride persistent over rows: removes wave-transition overhead
// ---------------------------------------------------------------------------
__global__ void __launch_bounds__(256)
rowsum_convert_kernel(const float* __restrict__ A) {
    __shared__ float red[8];
    for (int row = blockIdx.x; row < NN; row += gridDim.x) {
        const float4* a = reinterpret_cast<const float4*>(A + (size_t)row * NN);
        uint2* ah = reinterpret_cast<uint2*>(g_ah + (size_t)row * NN);
        float s = 0.f;
        #pragma unroll 8
        for (int i = threadIdx.x; i < NN / 4; i += 256) {
            float4 v = a[i];
            s += (v.x + v.y) + (v.z + v.w);
            __half2 h01 = __floats2half2_rn(v.x, v.y);
            __half2 h23 = __floats2half2_rn(v.z, v.w);
            uint2 u;
            u.x = *reinterpret_cast<uint32_t*>(&h01);
            u.y = *reinterpret_cast<uint32_t*>(&h23);
            ah[i] = u;
        }
        #pragma unroll
        for (int o = 16; o; o >>= 1) s += __shfl_xor_sync(0xFFFFFFFFu, s, o);
        if ((threadIdx.x & 31) == 0) red[threadIdx.x >> 5] = s;
        __syncthreads();
        if (threadIdx.x < 32) {
            s = (threadIdx.x < 8) ? red[threadIdx.x] : 0.f;
            #pragma unroll
            for (int o = 4; o; o >>= 1) s += __shfl_xor_sync(0xFFFFFFFFu, s, o);
            if (threadIdx.x == 0) g_deg[row] = s;
        }
        __syncthreads();
    }
}

// ---------------------------------------------------------------------------
// Kernel 2: Y[j][k] = fp16( rsqrt(deg[j]) * sum_f X[j][f] * W[f][k] )
// ---------------------------------------------------------------------------
__global__ void xw_kernel(const float* __restrict__ X, const float* __restrict__ W) {
    __shared__ float sW[DIN * DOUT];   // 32 KB
    __shared__ float sX[16 * DIN];     // 8 KB
    int r0 = blockIdx.x * 16;
    for (int i = threadIdx.x; i < DIN * DOUT; i += 256) sW[i] = W[i];
    for (int i = threadIdx.x; i < 16 * DIN; i += 256) {
        int r = i >> 7, f = i & 127;
        sX[i] = X[(size_t)(r0 + r) * DIN + f] * rsqrtf(g_deg[r0 + r]);
    }
    __syncthreads();

    int r  = threadIdx.x >> 4;           // 0..15
    int c0 = (threadIdx.x & 15) * 4;     // 0..60
    float4 acc = make_float4(0.f, 0.f, 0.f, 0.f);
    #pragma unroll 8
    for (int f = 0; f < DIN; f++) {
        float s = sX[r * DIN + f];
        float4 w = *reinterpret_cast<const float4*>(&sW[f * DOUT + c0]);
        acc.x += s * w.x; acc.y += s * w.y; acc.z += s * w.z; acc.w += s * w.w;
    }
    __half2 h01 = __floats2half2_rn(acc.x, acc.y);
    __half2 h23 = __floats2half2_rn(acc.z, acc.w);
    uint2 u;
    u.x = *reinterpret_cast<uint32_t*>(&h01);
    u.y = *reinterpret_cast<uint32_t*>(&h23);
    *reinterpret_cast<uint2*>(&g_yh[(size_t)(r0 + r) * DOUT + c0]) = u;
}

// ---------------------------------------------------------------------------
// Kernel 3: split-K GEMM  g_hpart[split] = A_h_slice @ Y_slice (fp16 mma.sync)
// grid (64, 4) = 256 CTAs, block 256 (8 warps: 4 over M x 2 over N)
// 4-stage cp.async pipeline, 2 CTAs/SM
// ---------------------------------------------------------------------------
__device__ __forceinline__ void load_chunk(uint32_t sbase, int stage, int c,
                                           const __half* __restrict__ Ablk,
                                           const __half* __restrict__ Bblk, int tid) {
    const uint32_t sA = sbase + (uint32_t)stage * A_STAGE_BYTES;
    const uint32_t sB = sbase + SMEM_B_BASE + (uint32_t)stage * B_STAGE_BYTES;
    const __half* ap = Ablk + (size_t)c * K_TILE;
    const __half* bp = Bblk + (size_t)c * K_TILE * DOUT;
    // A: 128 rows x 128B -> 1024 x 16B -> 4 per thread
    #pragma unroll
    for (int it = 0; it < 4; it++) {
        int idx = tid + 256 * it;
        int row = idx >> 3;
        int cc  = idx & 7;
        uint32_t dst = sA + (uint32_t)row * 128 + ((uint32_t)(cc ^ (row & 7)) << 4);
        CP_ASYNC16(dst, ap + (size_t)row * NN + cc * 8);
    }
    // B: 64 rows x 128B -> 512 x 16B -> 2 per thread
    #pragma unroll
    for (int it = 0; it < 2; it++) {
        int idx = tid + 256 * it;
        int kr  = idx >> 3;
        int cc  = idx & 7;
        uint32_t dst = sB + (uint32_t)kr * 128 + ((uint32_t)(cc ^ (kr & 7)) << 4);
        CP_ASYNC16(dst, bp + (size_t)kr * DOUT + cc * 8);
    }
}

__global__ void __launch_bounds__(256, 2)
gemm_kernel() {
    extern __shared__ __align__(128) char smem[];
    const uint32_t sbase = smem_u32(smem);

    const int tid  = threadIdx.x;
    const int lane = tid & 31;
    const int wid  = tid >> 5;
    const int wm   = wid & 3;            // warp M group (32 rows)
    const int wn   = wid >> 2;           // warp N group (32 cols)
    const int Ar0  = wm * 32;
    const int Cn0  = wn * 32;

    const __half* Ablk = g_ah + (size_t)blockIdx.x * M_TILE * NN + (size_t)blockIdx.y * KPER;
    const __half* Bblk = g_yh + (size_t)blockIdx.y * KPER * DOUT;

    // ldmatrix per-lane geometry
    const int a_lrow = lane & 15;
    const int a_lk   = lane >> 4;        // 0/1 -> k 16B col-chunk
    const int b_lk   = lane & 15;
    const int b_ln8  = lane >> 4;        // 0/1 -> n 8-group

    float acc[2][4][4];
    #pragma unroll
    for (int mi = 0; mi < 2; mi++)
        #pragma unroll
        for (int ni = 0; ni < 4; ni++)
            #pragma unroll
            for (int q = 0; q < 4; q++) acc[mi][ni][q] = 0.f;

    // prologue: stages 0..2
    #pragma unroll
    for (int s = 0; s < STAGES - 1; s++) {
        load_chunk(sbase, s, s, Ablk, Bblk, tid);
        CP_COMMIT();
    }

    for (int c = 0; c < NCHUNK; c++) {
        CP_WAIT2();                       // exactly 3 groups pending -> chunk c resident
        __syncthreads();

        const int s = c & (STAGES - 1);
        const uint32_t sA = sbase + (uint32_t)s * A_STAGE_BYTES;
        const uint32_t sB = sbase + SMEM_B_BASE + (uint32_t)s * B_STAGE_BYTES;

        // commit a group EVERY iteration (empty at tail) to keep the wait invariant
        if (c + STAGES - 1 < NCHUNK)
            load_chunk(sbase, (c + STAGES - 1) & (STAGES - 1), c + STAGES - 1, Ablk, Bblk, tid);
        CP_COMMIT();

        #pragma unroll
        for (int kk = 0; kk < K_TILE / 16; kk++) {
            uint32_t af[2][4];
            #pragma unroll
            for (int mi = 0; mi < 2; mi++) {
                int r = Ar0 + mi * 16 + a_lrow;
                uint32_t addr = sA + (uint32_t)r * 128 +
                                ((uint32_t)((kk * 2 + a_lk) ^ (r & 7)) << 4);
                ldsm_x4(af[mi], addr);
            }
            uint32_t bf[2][4];
            #pragma unroll
            for (int nb = 0; nb < 2; nb++) {
                int kr = kk * 16 + b_lk;
                int n  = Cn0 + nb * 16 + b_ln8 * 8;
                uint32_t addr = sB + (uint32_t)kr * 128 +
                                ((uint32_t)((n >> 3) ^ (kr & 7)) << 4);
                ldsm_x4_t(bf[nb], addr);
            }
            #pragma unroll
            for (int mi = 0; mi < 2; mi++)
                #pragma unroll
                for (int ni = 0; ni < 4; ni++)
                    mma_f16(acc[mi][ni], af[mi], bf[ni >> 1][2 * (ni & 1)], bf[ni >> 1][2 * (ni & 1) + 1]);
        }
    }

    // epilogue: acc -> g_hpart[split]
    float* Hp = g_hpart[blockIdx.y];
    const int g = lane >> 2, q = lane & 3;
    const int R0 = blockIdx.x * M_TILE + wm * 32;
    #pragma unroll
    for (int mi = 0; mi < 2; mi++) {
        #pragma unroll
        for (int ni = 0; ni < 4; ni++) {
            int row = R0 + mi * 16 + g;
            int col = Cn0 + ni * 8 + q * 2;
            *reinterpret_cast<float2*>(&Hp[(size_t)row * DOUT + col]) =
                make_float2(acc[mi][ni][0], acc[mi][ni][1]);
            *reinterpret_cast<float2*>(&Hp[(size_t)(row + 8) * DOUT + col]) =
                make_float2(acc[mi][ni][2], acc[mi][ni][3]);
        }
    }
}

// ---------------------------------------------------------------------------
// Kernel 4: out = relu( d^-1/2_i * sum_s hpart[s] ); 2 float4 per thread
// ---------------------------------------------------------------------------
__global__ void out_kernel(float* __restrict__ out) {
    int t = blockIdx.x * 256 + threadIdx.x;          // 65536 threads
    #pragma unroll
    for (int h = 0; h < 2; h++) {
        int idx = t + h * 65536;                     // over 131072 float4s
        int row = idx >> 4;
        int c4  = (idx & 15) * 4;
        size_t o = (size_t)row * DOUT + c4;
        float4 a = *reinterpret_cast<const float4*>(&g_hpart[0][o]);
        float4 b = *reinterpret_cast<const float4*>(&g_hpart[1][o]);
        float4 cc = *reinterpret_cast<const float4*>(&g_hpart[2][o]);
        float4 d = *reinterpret_cast<const float4*>(&g_hpart[3][o]);
        float s = rsqrtf(g_deg[row]);
        float4 r;
        r.x = fmaxf((a.x + b.x + cc.x + d.x) * s, 0.f);
        r.y = fmaxf((a.y + b.y + cc.y + d.y) * s, 0.f);
        r.z = fmaxf((a.z + b.z + cc.z + d.z) * s, 0.f);
        r.w = fmaxf((a.w + b.w + cc.w + d.w) * s, 0.f);
        *reinterpret_cast<float4*>(&out[o]) = r;
    }
}

// ---------------------------------------------------------------------------
// Launch
// ---------------------------------------------------------------------------
extern "C" void kernel_launch(void* const* d_in, const int* in_sizes, int n_in,
                              void* d_out, int out_size) {
    const float* X = (const float*)d_in[0];   // features      [8192, 128]
    const float* A = (const float*)d_in[1];   // adjacency     [8192, 8192]
    const float* W = (const float*)d_in[2];   // weight        [128, 64]
    float* out = (float*)d_out;               // [8192, 64] fp32
    (void)in_sizes; (void)n_in; (void)out_size;

    static bool attr_set = false;
    if (!attr_set) {
        cudaFuncSetAttribute(gemm_kernel, cudaFuncAttributeMaxDynamicSharedMemorySize, SMEM_TOTAL);
        attr_set = true;
    }

    rowsum_convert_kernel<<<1184, 256>>>(A);   // 8 x 148 persistent blocks
    xw_kernel<<<NN / 16, 256>>>(X, W);
    gemm_kernel<<<dim3(NN / M_TILE, SPLITK), 256, SMEM_TOTAL>>>();
    out_kernel<<<256, 256>>>(out);
}